// round 3
// baseline (speedup 1.0000x reference)
#include <cuda_runtime.h>
#include <cuda_bf16.h>

#define BB 4
#define HH 16
#define SS 4096
#define DD 64
#define BH (BB*HH)
#define SPLIT 8
#define ROWS_P1 (SS/SPLIT)      // 512
#define CHUNK 16
#define NCH (ROWS_P1/CHUNK)     // 32
#define P2_TILE 256
#define QSTRIDE 68              // padded q row stride (bank-stagger)
#define KEPS 0.001f

typedef unsigned long long ull;

// Scratch: per-split partial kv / ksum (device globals: no allocs allowed)
__device__ float g_kv[BH][SPLIT][DD * DD];
__device__ float g_ksum[BH][SPLIT][DD];

// ---- packed fp32x2 helpers (sm_103a FFMA2 — only reachable via PTX) ----
__device__ __forceinline__ ull ffma2(ull a, ull b, ull c) {
    ull d;
    asm("fma.rn.f32x2 %0, %1, %2, %3;" : "=l"(d) : "l"(a), "l"(b), "l"(c));
    return d;
}
__device__ __forceinline__ ull pack2(float x) {
    ull d;
    asm("mov.b64 %0, {%1, %1};" : "=l"(d) : "f"(x));
    return d;
}
__device__ __forceinline__ ull packf2(float x, float y) {
    ull d;
    asm("mov.b64 %0, {%1, %2};" : "=l"(d) : "f"(x), "f"(y));
    return d;
}
__device__ __forceinline__ float2 unpack2(ull a) {
    float2 r;
    asm("mov.b64 {%0, %1}, %2;" : "=f"(r.x), "=f"(r.y) : "l"(a));
    return r;
}

// ---------------------------------------------------------------------------
// Pass 1: kv[d][e] += k'[r][d] * v[r][e],  ksum[d] += k'[r][d]
// 256 thr: eq=tid&7 (8 e-groups, split halves), dq=(tid>>3)&7 (8 d), rr=tid>>6
// (4-way row split). 8d x 8e register tile; cross-rr reduction via smem at end.
// ---------------------------------------------------------------------------
__global__ __launch_bounds__(256) void perf_pass1(
    const float* __restrict__ K,
    const float* __restrict__ V,
    const float* __restrict__ mask)
{
    const int bh = blockIdx.x / SPLIT;
    const int sp = blockIdx.x % SPLIT;
    const int b  = bh / HH;

    const float* Kp = K + (size_t)bh * SS * DD + (size_t)sp * ROWS_P1 * DD;
    const float* Vp = V + (size_t)bh * SS * DD + (size_t)sp * ROWS_P1 * DD;
    const float* Mp = mask + (size_t)b * SS + (size_t)sp * ROWS_P1;

    __shared__ float ks[2][CHUNK][DD];
    __shared__ float vs[2][CHUNK][DD];
    __shared__ float ksred[4][DD];
    __shared__ float red[4][16][DD];   // cross-rr reduction buffer (16KB)

    const int tid = threadIdx.x;
    const int eq = tid & 7;
    const int dq = (tid >> 3) & 7;
    const int rr = tid >> 6;
    const int srow = tid >> 4;          // staging row within chunk
    const int scol = (tid & 15) * 4;    // staging col

    ull acc[8][4];
#pragma unroll
    for (int i = 0; i < 8; i++)
#pragma unroll
        for (int j = 0; j < 4; j++) acc[i][j] = 0ULL;
    float ksacc[8] = {0, 0, 0, 0, 0, 0, 0, 0};

    // prefetch chunk 0
    float4 kreg = *reinterpret_cast<const float4*>(&Kp[(size_t)srow * DD + scol]);
    float4 vreg = *reinterpret_cast<const float4*>(&Vp[(size_t)srow * DD + scol]);
    float  mreg = Mp[srow];

    for (int c = 0; c < NCH; c++) {
        const int buf = c & 1;
        float4 kf;
        kf.x = (fmaxf(kreg.x, 0.f) + KEPS) * mreg;
        kf.y = (fmaxf(kreg.y, 0.f) + KEPS) * mreg;
        kf.z = (fmaxf(kreg.z, 0.f) + KEPS) * mreg;
        kf.w = (fmaxf(kreg.w, 0.f) + KEPS) * mreg;
        *reinterpret_cast<float4*>(&ks[buf][srow][scol]) = kf;
        *reinterpret_cast<float4*>(&vs[buf][srow][scol]) = vreg;
        __syncthreads();

        if (c + 1 < NCH) {
            const size_t off = (size_t)(c + 1) * CHUNK * DD + (size_t)srow * DD + scol;
            kreg = *reinterpret_cast<const float4*>(&Kp[off]);
            vreg = *reinterpret_cast<const float4*>(&Vp[off]);
            mreg = Mp[(c + 1) * CHUNK + srow];
        }

#pragma unroll
        for (int r0 = 0; r0 < CHUNK; r0 += 4) {
            const int r = r0 + rr;
            const float4 ka = *reinterpret_cast<const float4*>(&ks[buf][r][dq * 8]);
            const float4 kb = *reinterpret_cast<const float4*>(&ks[buf][r][dq * 8 + 4]);
            const ulonglong2 va = *reinterpret_cast<const ulonglong2*>(&vs[buf][r][eq * 4]);
            const ulonglong2 vb = *reinterpret_cast<const ulonglong2*>(&vs[buf][r][eq * 4 + 32]);
            const float kd[8] = {ka.x, ka.y, ka.z, ka.w, kb.x, kb.y, kb.z, kb.w};
#pragma unroll
            for (int i = 0; i < 8; i++) {
                const ull kp = pack2(kd[i]);
                acc[i][0] = ffma2(kp, va.x, acc[i][0]);
                acc[i][1] = ffma2(kp, va.y, acc[i][1]);
                acc[i][2] = ffma2(kp, vb.x, acc[i][2]);
                acc[i][3] = ffma2(kp, vb.y, acc[i][3]);
            }
            if (eq == 0) {
#pragma unroll
                for (int i = 0; i < 8; i++) ksacc[i] += kd[i];
            }
        }
    }

    // stash per-rr ksum partials (reduced after the kv chunks' syncs)
    if (eq == 0) {
#pragma unroll
        for (int i = 0; i < 8; i++) ksred[rr][dq * 8 + i] = ksacc[i];
    }

    // ---- cross-rr reduction of kv tiles: 4 chunks of 2 d-rows each ----
    float* kvp = g_kv[bh][sp];
#pragma unroll
    for (int i0 = 0; i0 < 8; i0 += 2) {
        __syncthreads();   // red buffer free (prev chunk consumed / mainloop done)
#pragma unroll
        for (int j = 0; j < 2; j++) {
            ull* dst = reinterpret_cast<ull*>(&red[rr][dq * 2 + j][0]);
            dst[eq * 2]          = acc[i0 + j][0];
            dst[eq * 2 + 1]      = acc[i0 + j][1];
            dst[16 + eq * 2]     = acc[i0 + j][2];
            dst[16 + eq * 2 + 1] = acc[i0 + j][3];
        }
        __syncthreads();
        // 1024 outputs this chunk; 4 floats per thread, summed over 4 rr copies
        const float* base = &red[0][0][0];
        float4 s = *reinterpret_cast<const float4*>(base + tid * 4);
#pragma unroll
        for (int p = 1; p < 4; p++) {
            const float4 v = *reinterpret_cast<const float4*>(base + p * 1024 + tid * 4);
            s.x += v.x; s.y += v.y; s.z += v.z; s.w += v.w;
        }
        const int o    = tid * 4;
        const int dloc = o >> 6;                       // 0..15
        const int e    = o & 63;
        const int dg   = (dloc >> 1) * 8 + i0 + (dloc & 1);
        *reinterpret_cast<float4*>(&kvp[(size_t)dg * DD + e]) = s;
    }

    __syncthreads();
    if (tid < DD)
        g_ksum[bh][sp][tid] = ksred[0][tid] + ksred[1][tid] + ksred[2][tid] + ksred[3][tid];
}

// ---------------------------------------------------------------------------
// Pass 2: out[s,e] = (q'[s,:] . kv[:,e]) / (q'[s,:] . ksum)
// 256 thr: eq=tid&7 (8 e, split halves), rq=tid>>3 (32 x 8 rows = 256 rows).
// Denominator fused into the d-loop; q rows padded to stride 68 (bank stagger).
// ---------------------------------------------------------------------------
__global__ __launch_bounds__(256) void perf_pass2(
    const float* __restrict__ Q,
    float* __restrict__ O)
{
    extern __shared__ float sm[];
    float* kv   = sm;                        // DD*DD = 4096
    float* qs   = sm + DD * DD;              // P2_TILE*QSTRIDE = 17408
    float* ksum = qs + P2_TILE * QSTRIDE;    // DD

    const int bh   = blockIdx.x >> 4;
    const int tile = blockIdx.x & 15;
    const int tid  = threadIdx.x;
    const int eq   = tid & 7;
    const int rq   = tid >> 3;

    // reduce kv partials (16 floats per thread, vectorized)
#pragma unroll
    for (int i = 0; i < 4; i++) {
        const int idx = tid * 4 + i * 1024;
        float4 s = make_float4(0.f, 0.f, 0.f, 0.f);
#pragma unroll
        for (int p = 0; p < SPLIT; p++) {
            const float4 v = *reinterpret_cast<const float4*>(&g_kv[bh][p][idx]);
            s.x += v.x; s.y += v.y; s.z += v.z; s.w += v.w;
        }
        *reinterpret_cast<float4*>(&kv[idx]) = s;
    }
    if (tid < DD) {
        float s = 0.f;
#pragma unroll
        for (int p = 0; p < SPLIT; p++) s += g_ksum[bh][p][tid];
        ksum[tid] = s;
    }

    // stage + featurize q tile (256 rows, padded stride)
    const float* Qp = Q + (size_t)bh * SS * DD + (size_t)tile * P2_TILE * DD;
    float*       Op = O + (size_t)bh * SS * DD + (size_t)tile * P2_TILE * DD;
#pragma unroll
    for (int i = 0; i < 16; i++) {
        const int idx = tid * 4 + i * 1024;
        float4 v = *reinterpret_cast<const float4*>(&Qp[idx]);
        v.x = fmaxf(v.x, 0.f) + KEPS;
        v.y = fmaxf(v.y, 0.f) + KEPS;
        v.z = fmaxf(v.z, 0.f) + KEPS;
        v.w = fmaxf(v.w, 0.f) + KEPS;
        const int r = idx >> 6, c = idx & 63;
        *reinterpret_cast<float4*>(&qs[r * QSTRIDE + c]) = v;
    }
    __syncthreads();

    ull acc[8][4];
#pragma unroll
    for (int i = 0; i < 8; i++)
#pragma unroll
        for (int j = 0; j < 4; j++) acc[i][j] = 0ULL;
    ull dacc[8];
#pragma unroll
    for (int i = 0; i < 8; i++) dacc[i] = 0ULL;

    for (int d = 0; d < DD; d += 4) {
        const ulonglong2 ks2 = *reinterpret_cast<const ulonglong2*>(&ksum[d]);
        float4 q4[8];
#pragma unroll
        for (int i = 0; i < 8; i++)
            q4[i] = *reinterpret_cast<const float4*>(&qs[(rq * 8 + i) * QSTRIDE + d]);

        // fused denominator (pairs over d)
#pragma unroll
        for (int i = 0; i < 8; i++) {
            dacc[i] = ffma2(packf2(q4[i].x, q4[i].y), ks2.x, dacc[i]);
            dacc[i] = ffma2(packf2(q4[i].z, q4[i].w), ks2.y, dacc[i]);
        }

#pragma unroll
        for (int dd = 0; dd < 4; dd++) {
            const float* kvrow = &kv[(size_t)(d + dd) * DD];
            const ulonglong2 kva = *reinterpret_cast<const ulonglong2*>(&kvrow[eq * 4]);
            const ulonglong2 kvb = *reinterpret_cast<const ulonglong2*>(&kvrow[eq * 4 + 32]);
#pragma unroll
            for (int i = 0; i < 8; i++) {
                const float qv = (dd == 0) ? q4[i].x : (dd == 1) ? q4[i].y
                               : (dd == 2) ? q4[i].z : q4[i].w;
                const ull qb = pack2(qv);
                acc[i][0] = ffma2(qb, kva.x, acc[i][0]);
                acc[i][1] = ffma2(qb, kva.y, acc[i][1]);
                acc[i][2] = ffma2(qb, kvb.x, acc[i][2]);
                acc[i][3] = ffma2(qb, kvb.y, acc[i][3]);
            }
        }
    }

    // scale by 1/denom and write out
#pragma unroll
    for (int i = 0; i < 8; i++) {
        const float2 dp = unpack2(dacc[i]);
        const float inv = 1.0f / (dp.x + dp.y);
        const float2 a0 = unpack2(acc[i][0]);
        const float2 a1 = unpack2(acc[i][1]);
        const float2 a2 = unpack2(acc[i][2]);
        const float2 a3 = unpack2(acc[i][3]);
        const int row = rq * 8 + i;
        float4 o0 = make_float4(a0.x * inv, a0.y * inv, a1.x * inv, a1.y * inv);
        float4 o1 = make_float4(a2.x * inv, a2.y * inv, a3.x * inv, a3.y * inv);
        *reinterpret_cast<float4*>(&Op[(size_t)row * DD + eq * 4])      = o0;
        *reinterpret_cast<float4*>(&Op[(size_t)row * DD + eq * 4 + 32]) = o1;
    }
}

#define SMEM_P2 ((DD * DD + P2_TILE * QSTRIDE + DD) * (int)sizeof(float))

extern "C" void kernel_launch(void* const* d_in, const int* in_sizes, int n_in,
                              void* d_out, int out_size)
{
    const float* Q = (const float*)d_in[0];
    const float* K = (const float*)d_in[1];
    const float* V = (const float*)d_in[2];
    const float* M = (const float*)d_in[3];
    float* O = (float*)d_out;

    cudaFuncSetAttribute(perf_pass2, cudaFuncAttributeMaxDynamicSharedMemorySize, SMEM_P2);

    perf_pass1<<<BH * SPLIT, 256>>>(K, V, M);
    perf_pass2<<<BH * 16, 256, SMEM_P2>>>(Q, O);
}

// round 4
// speedup vs baseline: 1.3018x; 1.3018x over previous
#include <cuda_runtime.h>
#include <cuda_bf16.h>

#define BB 4
#define HH 16
#define SS 4096
#define DD 64
#define BH (BB*HH)
#define SPLIT 8
#define RR 4
#define SPLITX (SPLIT*RR)       // 32 kv partials per head
#define ROWS_P1 (SS/SPLIT)      // 512
#define CHUNK 16
#define NCH (ROWS_P1/CHUNK)     // 32
#define P2_TILE 256
#define KEPS 0.001f

typedef unsigned long long ull;

// Scratch (device globals: no allocs allowed)
__device__ float g_kv[BH][SPLITX][DD * DD];   // 33.5 MB partials
__device__ float g_ksum[BH][SPLIT][DD];
__device__ float g_kvf[BH][DD * DD];          // reduced
__device__ float g_ksumf[BH][DD];

// ---- packed fp32x2 helpers (sm_103a FFMA2 — only via PTX) ----
__device__ __forceinline__ ull ffma2(ull a, ull b, ull c) {
    ull d;
    asm("fma.rn.f32x2 %0, %1, %2, %3;" : "=l"(d) : "l"(a), "l"(b), "l"(c));
    return d;
}
__device__ __forceinline__ ull pack2(float x) {
    ull d;
    asm("mov.b64 %0, {%1, %1};" : "=l"(d) : "f"(x));
    return d;
}
__device__ __forceinline__ ull packf2(float x, float y) {
    ull d;
    asm("mov.b64 %0, {%1, %2};" : "=l"(d) : "f"(x), "f"(y));
    return d;
}
__device__ __forceinline__ float2 unpack2(ull a) {
    float2 r;
    asm("mov.b64 {%0, %1}, %2;" : "=f"(r.x), "=f"(r.y) : "l"(a));
    return r;
}

// ---------------------------------------------------------------------------
// Pass 1: per (bh, sp) block; rr = tid>>6 splits rows 4-way, each rr-group
// accumulates its OWN partial -> g_kv[bh][sp*4+rr]. No in-block reduction.
// Thread tile: 8d x 8e (e split in two 32-wide halves). 2 blocks/SM.
// ---------------------------------------------------------------------------
__global__ __launch_bounds__(256, 2) void perf_pass1(
    const float* __restrict__ K,
    const float* __restrict__ V,
    const float* __restrict__ mask)
{
    const int bh = blockIdx.x / SPLIT;
    const int sp = blockIdx.x % SPLIT;
    const int b  = bh / HH;

    const float* Kp = K + (size_t)bh * SS * DD + (size_t)sp * ROWS_P1 * DD;
    const float* Vp = V + (size_t)bh * SS * DD + (size_t)sp * ROWS_P1 * DD;
    const float* Mp = mask + (size_t)b * SS + (size_t)sp * ROWS_P1;

    __shared__ float ks[2][CHUNK][DD];
    __shared__ float vs[2][CHUNK][DD];

    const int tid = threadIdx.x;
    const int eq = tid & 7;
    const int dq = (tid >> 3) & 7;
    const int rr = tid >> 6;
    const int srow = tid >> 4;
    const int scol = (tid & 15) * 4;

    ull acc[8][4];
#pragma unroll
    for (int i = 0; i < 8; i++)
#pragma unroll
        for (int j = 0; j < 4; j++) acc[i][j] = 0ULL;
    float ksacc = 0.f;   // only meaningful for tid < 64 (d = tid)

    float4 kreg = *reinterpret_cast<const float4*>(&Kp[(size_t)srow * DD + scol]);
    float4 vreg = *reinterpret_cast<const float4*>(&Vp[(size_t)srow * DD + scol]);
    float  mreg = Mp[srow];

    for (int c = 0; c < NCH; c++) {
        const int buf = c & 1;
        float4 kf;
        kf.x = (fmaxf(kreg.x, 0.f) + KEPS) * mreg;
        kf.y = (fmaxf(kreg.y, 0.f) + KEPS) * mreg;
        kf.z = (fmaxf(kreg.z, 0.f) + KEPS) * mreg;
        kf.w = (fmaxf(kreg.w, 0.f) + KEPS) * mreg;
        *reinterpret_cast<float4*>(&ks[buf][srow][scol]) = kf;
        *reinterpret_cast<float4*>(&vs[buf][srow][scol]) = vreg;
        __syncthreads();

        if (c + 1 < NCH) {
            const size_t off = (size_t)(c + 1) * CHUNK * DD + (size_t)srow * DD + scol;
            kreg = *reinterpret_cast<const float4*>(&Kp[off]);
            vreg = *reinterpret_cast<const float4*>(&Vp[off]);
            mreg = Mp[(c + 1) * CHUNK + srow];
        }

        // ksum accumulation on warps 0-1 (d = tid), reading staged (masked) k
        if (tid < DD) {
#pragma unroll
            for (int r = 0; r < CHUNK; r++) ksacc += ks[buf][r][tid];
        }

#pragma unroll
        for (int r0 = 0; r0 < CHUNK; r0 += RR) {
            const int r = r0 + rr;
            const float4 ka = *reinterpret_cast<const float4*>(&ks[buf][r][dq * 8]);
            const float4 kb = *reinterpret_cast<const float4*>(&ks[buf][r][dq * 8 + 4]);
            const ulonglong2 va = *reinterpret_cast<const ulonglong2*>(&vs[buf][r][eq * 4]);
            const ulonglong2 vb = *reinterpret_cast<const ulonglong2*>(&vs[buf][r][eq * 4 + 32]);
            const float kd[8] = {ka.x, ka.y, ka.z, ka.w, kb.x, kb.y, kb.z, kb.w};
#pragma unroll
            for (int i = 0; i < 8; i++) {
                const ull kp = pack2(kd[i]);
                acc[i][0] = ffma2(kp, va.x, acc[i][0]);
                acc[i][1] = ffma2(kp, va.y, acc[i][1]);
                acc[i][2] = ffma2(kp, vb.x, acc[i][2]);
                acc[i][3] = ffma2(kp, vb.y, acc[i][3]);
            }
        }
    }

    // write this rr-group's partial
    float* kvp = g_kv[bh][(sp << 2) | rr];
#pragma unroll
    for (int i = 0; i < 8; i++) {
        ull* row = reinterpret_cast<ull*>(kvp + (size_t)(dq * 8 + i) * DD);
        row[eq * 2]          = acc[i][0];
        row[eq * 2 + 1]      = acc[i][1];
        row[16 + eq * 2]     = acc[i][2];
        row[16 + eq * 2 + 1] = acc[i][3];
    }
    if (tid < DD) g_ksum[bh][sp][tid] = ksacc;
}

// ---------------------------------------------------------------------------
// Reduce: sum the 32 kv partials and 8 ksum partials per head.
// 4 blocks per head, each handles a quarter of the 64x64 kv.
// ---------------------------------------------------------------------------
__global__ __launch_bounds__(256) void perf_reduce()
{
    const int bh = blockIdx.x >> 2;
    const int qt = blockIdx.x & 3;
    const int tid = threadIdx.x;
    const int idx = qt * 1024 + tid * 4;

    float4 s = make_float4(0.f, 0.f, 0.f, 0.f);
#pragma unroll
    for (int p = 0; p < SPLITX; p++) {
        const float4 v = *reinterpret_cast<const float4*>(&g_kv[bh][p][idx]);
        s.x += v.x; s.y += v.y; s.z += v.z; s.w += v.w;
    }
    *reinterpret_cast<float4*>(&g_kvf[bh][idx]) = s;

    if (qt == 0 && tid < DD) {
        float t = 0.f;
#pragma unroll
        for (int p = 0; p < SPLIT; p++) t += g_ksum[bh][p][tid];
        g_ksumf[bh][tid] = t;
    }
}

// ---------------------------------------------------------------------------
// Pass 2: out[s,e] = (q'[s,:] . kv[:,e]) / (q'[s,:] . ksum)
// 256 thr: eq=tid&7 (8 e, two halves), rq=tid>>3 (32 groups x 8 rows).
// qs stride 64 with per-row column rotation ((r>>3)&3)*4 -> conflict-free.
// ---------------------------------------------------------------------------
__global__ __launch_bounds__(256, 2) void perf_pass2(
    const float* __restrict__ Q,
    float* __restrict__ O)
{
    extern __shared__ float sm[];
    float* kv   = sm;                     // 4096
    float* qs   = sm + DD * DD;           // P2_TILE * 64 = 16384
    float* ksum = qs + P2_TILE * DD;      // 64

    const int bh   = blockIdx.x >> 4;
    const int tile = blockIdx.x & 15;
    const int tid  = threadIdx.x;
    const int eq   = tid & 7;
    const int rq   = tid >> 3;

    // load reduced kv / ksum
#pragma unroll
    for (int i = 0; i < 4; i++) {
        const int idx = tid * 4 + i * 1024;
        *reinterpret_cast<float4*>(&kv[idx]) =
            *reinterpret_cast<const float4*>(&g_kvf[bh][idx]);
    }
    if (tid < DD) ksum[tid] = g_ksumf[bh][tid];

    // stage + featurize q tile with rotation swizzle
    const float* Qp = Q + (size_t)bh * SS * DD + (size_t)tile * P2_TILE * DD;
    float*       Op = O + (size_t)bh * SS * DD + (size_t)tile * P2_TILE * DD;
#pragma unroll
    for (int i = 0; i < 16; i++) {
        const int idx = tid * 4 + i * 1024;
        float4 v = *reinterpret_cast<const float4*>(&Qp[idx]);
        v.x = fmaxf(v.x, 0.f) + KEPS;
        v.y = fmaxf(v.y, 0.f) + KEPS;
        v.z = fmaxf(v.z, 0.f) + KEPS;
        v.w = fmaxf(v.w, 0.f) + KEPS;
        const int r = idx >> 6;
        const int c = idx & 63;
        const int rot = ((r >> 3) & 3) * 4;
        *reinterpret_cast<float4*>(&qs[r * DD + ((c + rot) & 63)]) = v;
    }
    __syncthreads();

    ull acc[8][4];
#pragma unroll
    for (int i = 0; i < 8; i++)
#pragma unroll
        for (int j = 0; j < 4; j++) acc[i][j] = 0ULL;
    ull dacc[8];
#pragma unroll
    for (int i = 0; i < 8; i++) dacc[i] = 0ULL;

    const int rot = (rq & 3) * 4;   // rotation for this thread's 8 rows

    for (int d = 0; d < DD; d += 4) {
        const ulonglong2 ks2 = *reinterpret_cast<const ulonglong2*>(&ksum[d]);
        const int col = (d + rot) & 63;
        float4 q4[8];
#pragma unroll
        for (int i = 0; i < 8; i++)
            q4[i] = *reinterpret_cast<const float4*>(&qs[(rq * 8 + i) * DD + col]);

        // fused denominator (pairs over d)
#pragma unroll
        for (int i = 0; i < 8; i++) {
            dacc[i] = ffma2(packf2(q4[i].x, q4[i].y), ks2.x, dacc[i]);
            dacc[i] = ffma2(packf2(q4[i].z, q4[i].w), ks2.y, dacc[i]);
        }

#pragma unroll
        for (int dd = 0; dd < 4; dd++) {
            const float* kvrow = &kv[(size_t)(d + dd) * DD];
            const ulonglong2 kva = *reinterpret_cast<const ulonglong2*>(&kvrow[eq * 4]);
            const ulonglong2 kvb = *reinterpret_cast<const ulonglong2*>(&kvrow[eq * 4 + 32]);
#pragma unroll
            for (int i = 0; i < 8; i++) {
                const float qv = (dd == 0) ? q4[i].x : (dd == 1) ? q4[i].y
                               : (dd == 2) ? q4[i].z : q4[i].w;
                const ull qb = pack2(qv);
                acc[i][0] = ffma2(qb, kva.x, acc[i][0]);
                acc[i][1] = ffma2(qb, kva.y, acc[i][1]);
                acc[i][2] = ffma2(qb, kvb.x, acc[i][2]);
                acc[i][3] = ffma2(qb, kvb.y, acc[i][3]);
            }
        }
    }

    // scale by 1/denom and write out
#pragma unroll
    for (int i = 0; i < 8; i++) {
        const float2 dp = unpack2(dacc[i]);
        const float inv = 1.0f / (dp.x + dp.y);
        const float2 a0 = unpack2(acc[i][0]);
        const float2 a1 = unpack2(acc[i][1]);
        const float2 a2 = unpack2(acc[i][2]);
        const float2 a3 = unpack2(acc[i][3]);
        const int row = rq * 8 + i;
        float4 o0 = make_float4(a0.x * inv, a0.y * inv, a1.x * inv, a1.y * inv);
        float4 o1 = make_float4(a2.x * inv, a2.y * inv, a3.x * inv, a3.y * inv);
        *reinterpret_cast<float4*>(&Op[(size_t)row * DD + eq * 4])      = o0;
        *reinterpret_cast<float4*>(&Op[(size_t)row * DD + eq * 4 + 32]) = o1;
    }
}

#define SMEM_P2 ((DD * DD + P2_TILE * DD + DD) * (int)sizeof(float))

extern "C" void kernel_launch(void* const* d_in, const int* in_sizes, int n_in,
                              void* d_out, int out_size)
{
    const float* Q = (const float*)d_in[0];
    const float* K = (const float*)d_in[1];
    const float* V = (const float*)d_in[2];
    const float* M = (const float*)d_in[3];
    float* O = (float*)d_out;

    cudaFuncSetAttribute(perf_pass2, cudaFuncAttributeMaxDynamicSharedMemorySize, SMEM_P2);

    perf_pass1<<<BH * SPLIT, 256>>>(K, V, M);
    perf_reduce<<<BH * 4, 256>>>();
    perf_pass2<<<BH * 16, 256, SMEM_P2>>>(Q, O);
}